// round 3
// baseline (speedup 1.0000x reference)
#include <cuda_runtime.h>

typedef unsigned long long ull;

#define NOBS 18
#define NACT 5
#define NIN  23          // obs + act
#define HD   64          // hidden
#define NZ   32
#define RB   8           // batch rows per block
#define TT   1024
#define BB   1024
#define NTH  256
#define GRID (BB / RB)   // 128 blocks

// fast nonlinearities (EX2 rel err ~2^-22, RCP-div ~2^-21; tol is 1e-3 rel)
__device__ __forceinline__ float fsig(float x) {
    return __fdividef(1.0f, 1.0f + __expf(-x));
}
__device__ __forceinline__ float ftanh(float x) {
    float e = __expf(-2.0f * x);
    return __fdividef(1.0f - e, 1.0f + e);
}

// packed fp32x2 FMA: acc.{lo,hi} += a.{lo,hi} * b.{lo,hi}
#define FMA2(acc, a, b) \
    asm("fma.rn.f32x2 %0, %1, %2, %0;" : "+l"(acc) : "l"(a), "l"(b))

__device__ __forceinline__ float lo32(ull a) { return __uint_as_float((unsigned)a); }
__device__ __forceinline__ float hi32(ull a) { return __uint_as_float((unsigned)(a >> 32)); }

__global__ void __launch_bounds__(NTH, 1)
wm_kernel(const float* __restrict__ obs,  const float* __restrict__ actp,
          const float* __restrict__ h0,   const float* __restrict__ c0,
          const float* __restrict__ Wenc, const float* __restrict__ benc,
          const float* __restrict__ Wih,  const float* __restrict__ Whh,
          const float* __restrict__ bih,  const float* __restrict__ bhh,
          const float* __restrict__ Wpred,const float* __restrict__ bpred,
          const float* __restrict__ Wz,   const float* __restrict__ bz,
          float* __restrict__ out)
{
    // hx[r*66 + k] holds the pair (h[r][k], x[r][k]) as two f32 in one 8B slot
    __shared__ __align__(16) double hx[RB * 66];
    __shared__ __align__(8)  float h_s[RB][HD];     // compact h copy for heads
    __shared__ float c_s[RB][HD];
    __shared__ float act_s[RB][256];
    __shared__ __align__(8) float in_s[RB][24];     // raw obs||act for next step
    __shared__ __align__(8) float Wenc_s[HD][26];   // padded 23->26 (8B-aligned rows)
    __shared__ __align__(8) float Wpred_s[NOBS][66];
    __shared__ __align__(8) float Wz_s[NZ][66];
    __shared__ float benc_s[HD];

    const int tid = threadIdx.x;
    const int b0  = blockIdx.x * RB;

    // ---- personal gate weights: gate g = tid; pack (Whh[g][k], Wih[g][k]) ----
    ull w[64];
    {
        const float4* wh4 = (const float4*)(Whh + tid * HD);
        const float4* wi4 = (const float4*)(Wih + tid * HD);
        #pragma unroll
        for (int q = 0; q < 16; ++q) {
            float4 a = wh4[q];
            float4 b = wi4[q];
            w[4*q+0] = (ull)__float_as_uint(a.x) | ((ull)__float_as_uint(b.x) << 32);
            w[4*q+1] = (ull)__float_as_uint(a.y) | ((ull)__float_as_uint(b.y) << 32);
            w[4*q+2] = (ull)__float_as_uint(a.z) | ((ull)__float_as_uint(b.z) << 32);
            w[4*q+3] = (ull)__float_as_uint(a.w) | ((ull)__float_as_uint(b.w) << 32);
        }
    }
    const float bias_g = bih[tid] + bhh[tid];
    const int   gtype  = tid >> 6;   // 0:i 1:f 2:g 3:o (warp-uniform)

    // ---- cooperative smem weight loads ----
    for (int i = tid; i < HD * NIN;  i += NTH) Wenc_s[i / NIN][i % NIN] = Wenc[i];
    for (int i = tid; i < NOBS * HD; i += NTH) Wpred_s[i / HD][i % HD]  = Wpred[i];
    for (int i = tid; i < NZ * HD;   i += NTH) Wz_s[i / HD][i % HD]     = Wz[i];
    if (tid < HD) benc_s[tid] = benc[tid];

    // ---- h0 / c0 ----
    for (int i = tid; i < RB * HD; i += NTH) {
        int r = i >> 6, k = i & 63;
        float hv = h0[(b0 + r) * HD + k];
        ((float*)&hx[r * 66 + k])[0] = hv;
        h_s[r][k] = hv;
        c_s[r][k] = c0[(b0 + r) * HD + k];
    }

    // ---- raw-input prefetch lanes (184 loads/step: 8 rows x (18 obs + 5 act)) ----
    float*       psm = 0;
    const float* pg  = 0;
    int          pstride = 0;
    if (tid < 144) {
        int r = tid / 18, j = tid % 18;
        psm = &in_s[r][j];
        pg  = obs + (long)(b0 + r) * TT * NOBS + j;
        pstride = NOBS;
    } else if (tid < 184) {
        int q = tid - 144;
        int r = q / 5, j = q % 5;
        psm = &in_s[r][18 + j];
        pg  = actp + (long)(b0 + r) * TT * NACT + j;
        pstride = NACT;
    }

    // load raw t=0
    if (psm) *psm = pg[0];
    __syncthreads();

    // encoder for t=0 -> hx[..] x-half
    #pragma unroll
    for (int it = 0; it < 2; ++it) {
        int id = tid + it * NTH;      // 0..511
        int r = id >> 6, j = id & 63;
        const ull* wp = (const ull*)&Wenc_s[j][0];
        const ull* xp = (const ull*)&in_s[r][0];
        ull a2 = 0ULL;
        #pragma unroll
        for (int i = 0; i < 11; ++i) FMA2(a2, wp[i], xp[i]);
        float s = fmaf(Wenc_s[j][22], in_s[r][22], benc_s[j] + lo32(a2) + hi32(a2));
        ((float*)&hx[r * 66 + j])[1] = fmaxf(s, 0.0f);
    }
    // prefetch raw t=1
    float pf = 0.0f;
    if (psm) pf = pg[pstride];
    __syncthreads();

    // ---- output-head task setup: 400 tasks = 8 rows x (18 pred + 32 z) ----
    const long Z_BASE = (long)BB * TT * NOBS;
    int  r0 = tid / 50, o0 = tid % 50;
    bool sig0 = (o0 < NOBS);
    const ull* wr0 = sig0 ? (const ull*)&Wpred_s[o0][0] : (const ull*)&Wz_s[o0 - NOBS][0];
    float ob0 = sig0 ? bpred[o0] : bz[o0 - NOBS];
    float* pout0 = sig0 ? out + (long)(b0 + r0) * TT * NOBS + o0
                        : out + Z_BASE + (long)(b0 + r0) * TT * NZ + (o0 - NOBS);
    int os0 = sig0 ? NOBS : NZ;

    const bool has1 = (tid < 400 - NTH);
    int id1 = tid + NTH;
    int r1 = has1 ? id1 / 50 : 0, o1 = has1 ? id1 % 50 : 0;
    bool sig1 = (o1 < NOBS);
    const ull* wr1 = sig1 ? (const ull*)&Wpred_s[o1][0] : (const ull*)&Wz_s[o1 - NOBS][0];
    float ob1 = sig1 ? bpred[o1] : bz[o1 - NOBS];
    float* pout1 = sig1 ? out + (long)(b0 + r1) * TT * NOBS + o1
                        : out + Z_BASE + (long)(b0 + r1) * TT * NZ + (o1 - NOBS);
    int os1 = sig1 ? NOBS : NZ;

    // ================= main time loop =================
    for (int t = 0; t < TT; ++t) {
        // ---- A: fused gate GEMMs. acc.lo = Whh.h ; acc.hi = Wih.x ----
        ull acc[RB];
        #pragma unroll
        for (int r = 0; r < RB; ++r) acc[r] = 0ULL;
        #pragma unroll
        for (int k2 = 0; k2 < 32; ++k2) {
            #pragma unroll
            for (int r = 0; r < RB; ++r) {
                ulonglong2 hv = *(const ulonglong2*)(&hx[r * 66 + 2 * k2]); // LDS.128 bcast
                FMA2(acc[r], w[2 * k2],     hv.x);
                FMA2(acc[r], w[2 * k2 + 1], hv.y);
            }
        }

        // ---- B: nonlinearities -> act_s ----
        #pragma unroll
        for (int r = 0; r < RB; ++r) {
            float pre = lo32(acc[r]) + hi32(acc[r]) + bias_g;
            act_s[r][tid] = (gtype == 2) ? ftanh(pre) : fsig(pre);
        }
        __syncthreads();   // S1

        // ---- C: cell update (tasks (r,unit)) + stash raw input for t+1 ----
        if (psm) *psm = pf;
        #pragma unroll
        for (int it = 0; it < 2; ++it) {
            int id = tid + it * NTH;
            int r = id >> 6, u = id & 63;
            float si = act_s[r][u];
            float sf = act_s[r][64 + u];
            float tg = act_s[r][128 + u];
            float so = act_s[r][192 + u];
            float c = sf * c_s[r][u] + si * tg;
            c_s[r][u] = c;
            float hn = so * ftanh(c);
            ((float*)&hx[r * 66 + u])[0] = hn;
            h_s[r][u] = hn;
        }
        __syncthreads();   // S2

        // ---- D: heads (read h_s), encoder for t+1 (write x-half), prefetch t+2 ----
        {
            const ull* hp = (const ull*)&h_s[r0][0];
            ull a2 = 0ULL;
            #pragma unroll
            for (int k = 0; k < 32; ++k) FMA2(a2, wr0[k], hp[k]);
            float s = ob0 + lo32(a2) + hi32(a2);
            *pout0 = sig0 ? fsig(s) : s;
            pout0 += os0;
        }
        if (has1) {
            const ull* hp = (const ull*)&h_s[r1][0];
            ull a2 = 0ULL;
            #pragma unroll
            for (int k = 0; k < 32; ++k) FMA2(a2, wr1[k], hp[k]);
            float s = ob1 + lo32(a2) + hi32(a2);
            *pout1 = sig1 ? fsig(s) : s;
            pout1 += os1;
        }
        if (t + 1 < TT) {
            #pragma unroll
            for (int it = 0; it < 2; ++it) {
                int id = tid + it * NTH;
                int r = id >> 6, j = id & 63;
                const ull* wp = (const ull*)&Wenc_s[j][0];
                const ull* xp = (const ull*)&in_s[r][0];
                ull a2 = 0ULL;
                #pragma unroll
                for (int i = 0; i < 11; ++i) FMA2(a2, wp[i], xp[i]);
                float s = fmaf(Wenc_s[j][22], in_s[r][22], benc_s[j] + lo32(a2) + hi32(a2));
                ((float*)&hx[r * 66 + j])[1] = fmaxf(s, 0.0f);
            }
            if (psm && t + 2 < TT) pf = pg[(long)(t + 2) * pstride];
        }
        __syncthreads();   // S3
    }

    // ---- epilogue: hT, cT ----
    const long OUT_HC = (long)BB * TT * (NOBS + NZ);
    for (int i = tid; i < RB * HD; i += NTH) {
        int r = i >> 6, k = i & 63;
        out[OUT_HC + (long)(b0 + r) * HD + k] = h_s[r][k];
        out[OUT_HC + (long)BB * HD + (long)(b0 + r) * HD + k] = c_s[r][k];
    }
}

extern "C" void kernel_launch(void* const* d_in, const int* in_sizes, int n_in,
                              void* d_out, int out_size)
{
    (void)in_sizes; (void)n_in; (void)out_size;
    const float* obs   = (const float*)d_in[0];
    const float* actp  = (const float*)d_in[1];
    const float* h0    = (const float*)d_in[2];
    const float* c0    = (const float*)d_in[3];
    const float* Wenc  = (const float*)d_in[4];
    const float* benc  = (const float*)d_in[5];
    const float* Wih   = (const float*)d_in[6];
    const float* Whh   = (const float*)d_in[7];
    const float* bih   = (const float*)d_in[8];
    const float* bhh   = (const float*)d_in[9];
    const float* Wpred = (const float*)d_in[10];
    const float* bpred = (const float*)d_in[11];
    const float* Wz    = (const float*)d_in[12];
    const float* bz    = (const float*)d_in[13];
    float* out = (float*)d_out;

    wm_kernel<<<GRID, NTH>>>(obs, actp, h0, c0, Wenc, benc, Wih, Whh,
                             bih, bhh, Wpred, bpred, Wz, bz, out);
}

// round 4
// speedup vs baseline: 1.4026x; 1.4026x over previous
#include <cuda_runtime.h>

typedef unsigned long long ull;

#define NOBS 18
#define NACT 5
#define HD   64
#define NZ   32
#define RB   8
#define TT   1024
#define BB   1024
#define NTH1 512
#define GRID1 (BB / RB)      // 128 blocks

#define K2_ROWS 128
#define NTH2 256
#define GRID2 ((BB * TT) / K2_ROWS)   // 8192 blocks

// 256MB h-history scratch (allowed: __device__ global array)
__device__ float g_hh[(size_t)BB * TT * HD];

__device__ __forceinline__ float fsig(float x) {
    return __fdividef(1.0f, 1.0f + __expf(-x));
}
__device__ __forceinline__ float ftanh(float x) {
    float e = __expf(-2.0f * x);
    return __fdividef(1.0f - e, 1.0f + e);
}

#define FMA2(acc, a, b) \
    asm("fma.rn.f32x2 %0, %1, %2, %0;" : "+l"(acc) : "l"(a), "l"(b))

__device__ __forceinline__ float lo32(ull a) { return __uint_as_float((unsigned)a); }
__device__ __forceinline__ float hi32(ull a) { return __uint_as_float((unsigned)(a >> 32)); }
__device__ __forceinline__ ull packf(float lo, float hi) {
    return (ull)__float_as_uint(lo) | ((ull)__float_as_uint(hi) << 32);
}

// ==================== kernel 1: encoder + LSTM recurrence ====================
__global__ void __launch_bounds__(NTH1, 1)
lstm_kernel(const float* __restrict__ obs,  const float* __restrict__ actp,
            const float* __restrict__ h0,   const float* __restrict__ c0,
            const float* __restrict__ Wenc, const float* __restrict__ benc,
            const float* __restrict__ Wih,  const float* __restrict__ Whh,
            const float* __restrict__ bih,  const float* __restrict__ bhh,
            float* __restrict__ out)
{
    // hx[r*66 + k]: (h[r][k], x[r][k]) as two f32 in one 8B slot
    __shared__ __align__(16) double hx[RB * 66];                 // 4224 B
    __shared__ float part[4][RB][256];                           // 32768 B (part[0] doubles as act)
    __shared__ float c_s[RB][HD];                                // 2048 B
    __shared__ __align__(16) float in2[2][RB][24];               // 1536 B
    __shared__ __align__(8)  float Wenc_s[HD][26];               // 6656 B
    __shared__ float benc_s[HD];                                 // 256 B
    // total 47488 B < 48KB static limit

    const int tid  = threadIdx.x;
    const int b0   = blockIdx.x * RB;
    const int warp = tid >> 5, lane = tid & 31;
    const int q  = warp >> 2;              // k-quarter 0..3
    const int ks = q * 16;                 // k-range [ks, ks+16)
    const int gA = (warp & 3) * 64 + 2 * lane;   // this thread's gates: gA, gA+1

    // ---- personal gate weights: 2 gates x 16 k, packed (Whh lo, Wih hi) ----
    ull wA[16], wB[16];
    {
        const float* whA = Whh + gA * HD + ks;
        const float* wiA = Wih + gA * HD + ks;
        #pragma unroll
        for (int i = 0; i < 16; ++i) {
            wA[i] = packf(whA[i],      wiA[i]);
            wB[i] = packf(whA[HD + i], wiA[HD + i]);
        }
    }

    float biasg = 0.0f; int gt = 0;
    if (tid < 256) { biasg = bih[tid] + bhh[tid]; gt = tid >> 6; }

    // ---- shared weights ----
    for (int i = tid; i < HD * 23; i += NTH1) Wenc_s[i / 23][i % 23] = Wenc[i];
    if (tid < HD) benc_s[tid] = benc[tid];

    // ---- h0/c0: exactly 512 tasks ----
    const int hr = tid >> 6, hu = tid & 63;
    ((float*)&hx[hr * 66 + hu])[0] = h0[(b0 + hr) * HD + hu];
    c_s[hr][hu] = c0[(b0 + hr) * HD + hu];

    // ---- raw-input prefetch lanes: 184 = 8 rows x (18 obs + 5 act) ----
    float* psm0 = 0; float* psm1 = 0; const float* pg = 0; int pstr = 0;
    if (tid < 144) {
        int r = tid / 18, j = tid % 18;
        psm0 = &in2[0][r][j]; psm1 = &in2[1][r][j];
        pg = obs + (size_t)(b0 + r) * TT * NOBS + j; pstr = NOBS;
    } else if (tid < 184) {
        int u = tid - 144; int r = u / 5, j = u % 5;
        psm0 = &in2[0][r][18 + j]; psm1 = &in2[1][r][18 + j];
        pg = actp + (size_t)(b0 + r) * TT * NACT + j; pstr = NACT;
    }

    // raw_0 -> in2[1]
    if (psm1) *psm1 = pg[0];
    __syncthreads();

    // x_0 from in2[1] (512 tasks, one per thread)
    {
        const ull* wp = (const ull*)&Wenc_s[hu][0];
        const ull* xp = (const ull*)&in2[1][hr][0];
        ull a2 = 0ULL;
        #pragma unroll
        for (int i = 0; i < 11; ++i) FMA2(a2, wp[i], xp[i]);
        float s = fmaf(Wenc_s[hu][22], in2[1][hr][22], benc_s[hu] + lo32(a2) + hi32(a2));
        ((float*)&hx[hr * 66 + hu])[1] = fmaxf(s, 0.0f);
    }
    // invariant entering t=0: in2[0]=raw_1, pf=raw_2
    float pf = 0.0f;
    if (psm0) { *psm0 = pg[pstr]; pf = pg[2 * pstr]; }
    __syncthreads();

    float* hist = g_hh + (size_t)(b0 + hr) * TT * HD + hu;

    // ================= main time loop =================
    for (int t = 0; t < TT; ++t) {
        // ---- A: quarter-partial gate GEMMs (1 LDS.128 -> 4 FMA2) ----
        #pragma unroll
        for (int rg = 0; rg < 2; ++rg) {
            ull aA[4] = {0,0,0,0}, aB[4] = {0,0,0,0};
            #pragma unroll
            for (int i = 0; i < 8; ++i) {
                #pragma unroll
                for (int rr = 0; rr < 4; ++rr) {
                    const int r = rg * 4 + rr;
                    ulonglong2 hv = *(const ulonglong2*)&hx[r * 66 + ks + 2 * i];
                    FMA2(aA[rr], wA[2*i],   hv.x);
                    FMA2(aA[rr], wA[2*i+1], hv.y);
                    FMA2(aB[rr], wB[2*i],   hv.x);
                    FMA2(aB[rr], wB[2*i+1], hv.y);
                }
            }
            #pragma unroll
            for (int rr = 0; rr < 4; ++rr) {
                float2 p;
                p.x = lo32(aA[rr]) + hi32(aA[rr]);
                p.y = lo32(aB[rr]) + hi32(aB[rr]);
                *(float2*)&part[q][rg * 4 + rr][gA] = p;
            }
        }
        __syncthreads();   // S0

        // ---- B: warps 0-7: reduce + nonlin (+prefetch); warps 8-15: encoder t+1 ----
        if (tid < 256) {
            const int g = tid;
            #pragma unroll
            for (int r = 0; r < RB; ++r) {
                float pre = biasg + part[0][r][g] + part[1][r][g]
                                  + part[2][r][g] + part[3][r][g];
                part[0][r][g] = (gt == 2) ? ftanh(pre) : fsig(pre);  // act alias
            }
            if (psm0) {
                float* p = (t & 1) ? psm0 : psm1;    // in2[(t+1)&1]
                if (t + 2 < TT) *p = pf;
                if (t + 3 < TT) pf = pg[(size_t)(t + 3) * pstr];
            }
        } else if (t + 1 < TT) {
            const int id = tid - 256;
            #pragma unroll
            for (int it = 0; it < 2; ++it) {
                int idx = id + it * 256;
                int r = idx >> 6, j = idx & 63;       // r warp-uniform
                const float* xr = &in2[t & 1][r][0];  // raw_{t+1}
                const ull* wp = (const ull*)&Wenc_s[j][0];
                const ull* xp = (const ull*)xr;
                ull a2 = 0ULL;
                #pragma unroll
                for (int i = 0; i < 11; ++i) FMA2(a2, wp[i], xp[i]);
                float s = fmaf(Wenc_s[j][22], xr[22], benc_s[j] + lo32(a2) + hi32(a2));
                ((float*)&hx[r * 66 + j])[1] = fmaxf(s, 0.0f);
            }
        }
        __syncthreads();   // S1

        // ---- C: cell update, 512 tasks; stream h to history ----
        {
            float si = part[0][hr][hu];
            float sf = part[0][hr][64 + hu];
            float tg = part[0][hr][128 + hu];
            float so = part[0][hr][192 + hu];
            float c = sf * c_s[hr][hu] + si * tg;
            c_s[hr][hu] = c;
            float hn = so * ftanh(c);
            ((float*)&hx[hr * 66 + hu])[0] = hn;
            hist[(size_t)t * HD] = hn;
        }
        __syncthreads();   // S2
    }

    // ---- epilogue: hT, cT ----
    const size_t OUT_HC = (size_t)BB * TT * (NOBS + NZ);
    out[OUT_HC + (size_t)(b0 + hr) * HD + hu] = ((float*)&hx[hr * 66 + hu])[0];
    out[OUT_HC + (size_t)BB * HD + (size_t)(b0 + hr) * HD + hu] = c_s[hr][hu];
}

// ==================== kernel 2: output heads over h history ====================
__global__ void __launch_bounds__(NTH2, 2)
heads_kernel(const float* __restrict__ Wpred, const float* __restrict__ bpred,
             const float* __restrict__ Wz,    const float* __restrict__ bz,
             float* __restrict__ out)
{
    __shared__ __align__(16) float hs[K2_ROWS][HD];   // 32KB
    const int tid = threadIdx.x;
    const size_t row0 = (size_t)blockIdx.x * K2_ROWS;

    // cooperative h-tile load
    {
        const float4* src = (const float4*)(g_hh + row0 * HD);
        float4* dst = (float4*)&hs[0][0];
        for (int i = tid; i < K2_ROWS * HD / 4; i += NTH2) dst[i] = src[i];
    }

    const int o  = tid & 63;          // output index (50 active)
    const int rg = tid >> 6;          // row group 0..3 (32 rows each)
    const bool active = (o < 50);
    const bool isp = (o < NOBS);

    ull w[32]; float bias = 0.0f;
    if (active) {
        const ull* wr = (const ull*)(isp ? (Wpred + o * HD) : (Wz + (o - NOBS) * HD));
        #pragma unroll
        for (int k = 0; k < 32; ++k) w[k] = wr[k];
        bias = isp ? bpred[o] : bz[o - NOBS];
    }
    __syncthreads();

    if (active) {
        const size_t ZB = (size_t)BB * TT * NOBS;
        #pragma unroll 1
        for (int rb = 0; rb < 32; rb += 4) {
            ull a[4] = {0,0,0,0};
            #pragma unroll
            for (int k = 0; k < 16; ++k) {
                #pragma unroll
                for (int j = 0; j < 4; ++j) {
                    ulonglong2 hv = ((const ulonglong2*)&hs[rg * 32 + rb + j][0])[k];
                    FMA2(a[j], w[2*k],   hv.x);
                    FMA2(a[j], w[2*k+1], hv.y);
                }
            }
            #pragma unroll
            for (int j = 0; j < 4; ++j) {
                float s = bias + lo32(a[j]) + hi32(a[j]);
                size_t ridx = row0 + rg * 32 + rb + j;
                if (isp) out[ridx * NOBS + o] = fsig(s);
                else     out[ZB + ridx * NZ + (o - NOBS)] = s;
            }
        }
    }
}

extern "C" void kernel_launch(void* const* d_in, const int* in_sizes, int n_in,
                              void* d_out, int out_size)
{
    (void)in_sizes; (void)n_in; (void)out_size;
    const float* obs   = (const float*)d_in[0];
    const float* actp  = (const float*)d_in[1];
    const float* h0    = (const float*)d_in[2];
    const float* c0    = (const float*)d_in[3];
    const float* Wenc  = (const float*)d_in[4];
    const float* benc  = (const float*)d_in[5];
    const float* Wih   = (const float*)d_in[6];
    const float* Whh   = (const float*)d_in[7];
    const float* bih   = (const float*)d_in[8];
    const float* bhh   = (const float*)d_in[9];
    const float* Wpred = (const float*)d_in[10];
    const float* bpred = (const float*)d_in[11];
    const float* Wz    = (const float*)d_in[12];
    const float* bz    = (const float*)d_in[13];
    float* out = (float*)d_out;

    lstm_kernel<<<GRID1, NTH1>>>(obs, actp, h0, c0, Wenc, benc, Wih, Whh,
                                 bih, bhh, out);
    heads_kernel<<<GRID2, NTH2>>>(Wpred, bpred, Wz, bz, out);
}

// round 6
// speedup vs baseline: 1.4291x; 1.0189x over previous
#include <cuda_runtime.h>

typedef unsigned long long ull;

#define NOBS 18
#define NACT 5
#define HD   64
#define NZ   32
#define RB   7            // rows per block (max)
#define TT   1024
#define BB   1024
#define NTH1 512
#define GRID1 147         // ceil(1024/7); last block has 2 rows

#define K2_ROWS 128
#define NTH2 256
#define GRID2 ((BB * TT) / K2_ROWS)   // 8192 blocks

// 256MB h-history scratch (allowed: __device__ global array)
__device__ float g_hh[(size_t)BB * TT * HD];

__device__ __forceinline__ float fsig(float x) {
    return __fdividef(1.0f, 1.0f + __expf(-x));
}
__device__ __forceinline__ float ftanh(float x) {
    float e = __expf(-2.0f * x);
    return __fdividef(1.0f - e, 1.0f + e);
}

#define FMA2(acc, a, b) \
    asm("fma.rn.f32x2 %0, %1, %2, %0;" : "+l"(acc) : "l"(a), "l"(b))

__device__ __forceinline__ float lo32(ull a) { return __uint_as_float((unsigned)a); }
__device__ __forceinline__ float hi32(ull a) { return __uint_as_float((unsigned)(a >> 32)); }
__device__ __forceinline__ ull packf(float lo, float hi) {
    return (ull)__float_as_uint(lo) | ((ull)__float_as_uint(hi) << 32);
}

// ==================== kernel 1: encoder + LSTM recurrence ====================
__global__ void __launch_bounds__(NTH1, 1)
lstm_kernel(const float* __restrict__ obs,  const float* __restrict__ actp,
            const float* __restrict__ h0,   const float* __restrict__ c0,
            const float* __restrict__ Wenc, const float* __restrict__ benc,
            const float* __restrict__ Wih,  const float* __restrict__ Whh,
            const float* __restrict__ bih,  const float* __restrict__ bhh,
            float* __restrict__ out)
{
    __shared__ __align__(16) double hx[RB * 66];          // (h,x) pairs, 3696 B
    __shared__ float part[4][RB][256];                    // 28672 B (part[0] doubles as act)
    __shared__ float c_s[RB][HD];                         // 1792 B
    __shared__ __align__(16) float in2[2][RB][24];        // 1344 B
    __shared__ __align__(8)  float Wenc_s[HD][26];        // 6656 B
    __shared__ float benc_s[HD];                          // 256 B

    const int tid  = threadIdx.x;
    const int row0 = blockIdx.x * RB;
    const int warp = tid >> 5, lane = tid & 31;
    const int q  = warp >> 2;                  // k-quarter 0..3
    const int ks = q * 16;
    const int gA = (warp & 3) * 64 + 2 * lane; // gates gA, gA+1

    // ---- personal gate weights: 2 gates x 16 k, packed (Whh lo, Wih hi) ----
    ull wA[16], wB[16];
    {
        const float* whA = Whh + gA * HD + ks;
        const float* wiA = Wih + gA * HD + ks;
        #pragma unroll
        for (int i = 0; i < 16; ++i) {
            wA[i] = packf(whA[i],      wiA[i]);
            wB[i] = packf(whA[HD + i], wiA[HD + i]);
        }
    }

    float biasg = 0.0f; int gt = 0;
    if (tid < 256) { biasg = bih[tid] + bhh[tid]; gt = tid >> 6; }

    for (int i = tid; i < HD * 23; i += NTH1) Wenc_s[i / 23][i % 23] = Wenc[i];
    if (tid < HD) benc_s[tid] = benc[tid];

    // zero in2 (tail-block rows stay 0 forever)
    if (tid < 2 * RB * 24) ((float*)in2)[tid] = 0.0f;

    // ---- h0/c0 (RB*64 = 448 tasks) ----
    const int hr = tid >> 6, hu = tid & 63;
    const bool rowok = (hr < RB) && (row0 + hr < BB);
    if (hr < RB) {
        float hv = rowok ? h0[(row0 + hr) * HD + hu] : 0.0f;
        ((float*)&hx[hr * 66 + hu])[0] = hv;
        ((float*)&hx[hr * 66 + hu])[1] = 0.0f;
        c_s[hr][hu] = rowok ? c0[(row0 + hr) * HD + hu] : 0.0f;
    }
    __syncthreads();   // in2 zeroed before prefetch writes

    // ---- raw-input prefetch lanes: RB*23 = 161 ----
    float* psm0 = 0; float* psm1 = 0; const float* pg = 0; int pstr = 0;
    if (tid < RB * 23) {
        int r = tid / 23, j = tid % 23;
        if (row0 + r < BB) {
            psm0 = &in2[0][r][j]; psm1 = &in2[1][r][j];
            if (j < 18) { pg = obs  + (size_t)(row0 + r) * TT * NOBS + j;        pstr = NOBS; }
            else        { pg = actp + (size_t)(row0 + r) * TT * NACT + (j - 18); pstr = NACT; }
        }
    }

    if (psm1) *psm1 = pg[0];      // raw_0 -> in2[1]
    __syncthreads();

    // x_0 from in2[1] (448 tasks)
    if (hr < RB) {
        const ull* wp = (const ull*)&Wenc_s[hu][0];
        const ull* xp = (const ull*)&in2[1][hr][0];
        ull a2 = 0ULL;
        #pragma unroll
        for (int i = 0; i < 11; ++i) FMA2(a2, wp[i], xp[i]);
        float s = fmaf(Wenc_s[hu][22], in2[1][hr][22], benc_s[hu] + lo32(a2) + hi32(a2));
        ((float*)&hx[hr * 66 + hu])[1] = fmaxf(s, 0.0f);
    }
    float pf = 0.0f;
    if (psm0) { *psm0 = pg[pstr]; pf = pg[2 * pstr]; }   // in2[0]=raw_1, pf=raw_2
    __syncthreads();

    float* hist = rowok ? (g_hh + (size_t)(row0 + hr) * TT * HD + hu) : 0;

    // ================= main time loop =================
    for (int t = 0; t < TT; ++t) {
        // ---- A: quarter-partial gate GEMMs (1 LDS.128 -> 4 FMA2) ----
        {   // rows 0..3
            ull aA[4] = {0,0,0,0}, aB[4] = {0,0,0,0};
            #pragma unroll
            for (int i = 0; i < 8; ++i) {
                #pragma unroll
                for (int rr = 0; rr < 4; ++rr) {
                    ulonglong2 hv = *(const ulonglong2*)&hx[rr * 66 + ks + 2 * i];
                    FMA2(aA[rr], wA[2*i],   hv.x);
                    FMA2(aA[rr], wA[2*i+1], hv.y);
                    FMA2(aB[rr], wB[2*i],   hv.x);
                    FMA2(aB[rr], wB[2*i+1], hv.y);
                }
            }
            #pragma unroll
            for (int rr = 0; rr < 4; ++rr) {
                float2 p;
                p.x = lo32(aA[rr]) + hi32(aA[rr]);
                p.y = lo32(aB[rr]) + hi32(aB[rr]);
                *(float2*)&part[q][rr][gA] = p;
            }
        }
        {   // rows 4..6
            ull aA[3] = {0,0,0}, aB[3] = {0,0,0};
            #pragma unroll
            for (int i = 0; i < 8; ++i) {
                #pragma unroll
                for (int rr = 0; rr < 3; ++rr) {
                    ulonglong2 hv = *(const ulonglong2*)&hx[(4 + rr) * 66 + ks + 2 * i];
                    FMA2(aA[rr], wA[2*i],   hv.x);
                    FMA2(aA[rr], wA[2*i+1], hv.y);
                    FMA2(aB[rr], wB[2*i],   hv.x);
                    FMA2(aB[rr], wB[2*i+1], hv.y);
                }
            }
            #pragma unroll
            for (int rr = 0; rr < 3; ++rr) {
                float2 p;
                p.x = lo32(aA[rr]) + hi32(aA[rr]);
                p.y = lo32(aB[rr]) + hi32(aB[rr]);
                *(float2*)&part[q][4 + rr][gA] = p;
            }
        }
        __syncthreads();   // S0

        // ---- B: warps 0-7: reduce + nonlin (+prefetch); warps 8-15: encoder t+1 ----
        if (tid < 256) {
            const int g = tid;
            #pragma unroll
            for (int r = 0; r < RB; ++r) {
                float pre = biasg + part[0][r][g] + part[1][r][g]
                                  + part[2][r][g] + part[3][r][g];
                part[0][r][g] = (gt == 2) ? ftanh(pre) : fsig(pre);
            }
            if (psm0) {
                float* p = (t & 1) ? psm0 : psm1;    // in2[(t+1)&1]
                if (t + 2 < TT) *p = pf;
                if (t + 3 < TT) pf = pg[(size_t)(t + 3) * pstr];
            }
        } else if (t + 1 < TT) {
            const int id = tid - 256;
            #pragma unroll
            for (int it = 0; it < 2; ++it) {
                int idx = id + it * 256;
                int r = idx >> 6, j = idx & 63;
                if (r < RB) {
                    const float* xr = &in2[t & 1][r][0];   // raw_{t+1}
                    const ull* wp = (const ull*)&Wenc_s[j][0];
                    const ull* xp = (const ull*)xr;
                    ull a2 = 0ULL;
                    #pragma unroll
                    for (int i = 0; i < 11; ++i) FMA2(a2, wp[i], xp[i]);
                    float s = fmaf(Wenc_s[j][22], xr[22], benc_s[j] + lo32(a2) + hi32(a2));
                    ((float*)&hx[r * 66 + j])[1] = fmaxf(s, 0.0f);
                }
            }
        }
        __syncthreads();   // S1

        // ---- C: cell update (448 tasks); stream h to history ----
        if (hr < RB) {
            float si = part[0][hr][hu];
            float sf = part[0][hr][64 + hu];
            float tg = part[0][hr][128 + hu];
            float so = part[0][hr][192 + hu];
            float c = sf * c_s[hr][hu] + si * tg;
            c_s[hr][hu] = c;
            float hn = so * ftanh(c);
            ((float*)&hx[hr * 66 + hu])[0] = hn;
            if (hist) hist[(size_t)t * HD] = hn;
        }
        __syncthreads();   // S2
    }

    // ---- epilogue: hT, cT ----
    if (rowok) {
        const size_t OUT_HC = (size_t)BB * TT * (NOBS + NZ);
        out[OUT_HC + (size_t)(row0 + hr) * HD + hu] = ((float*)&hx[hr * 66 + hu])[0];
        out[OUT_HC + (size_t)BB * HD + (size_t)(row0 + hr) * HD + hu] = c_s[hr][hu];
    }
}

// ==================== kernel 2: output heads over h history ====================
// lane ℓ (0..24) owns outputs (2ℓ, 2ℓ+1); 1 LDS.128 of h feeds 4 FMA2.
__global__ void __launch_bounds__(NTH2, 1)
heads_kernel(const float* __restrict__ Wpred, const float* __restrict__ bpred,
             const float* __restrict__ Wz,    const float* __restrict__ bz,
             float* __restrict__ out)
{
    __shared__ __align__(16) float hs[K2_ROWS][HD];   // 32KB
    const int tid  = threadIdx.x;
    const int warp = tid >> 5, lane = tid & 31;
    const size_t row0 = (size_t)blockIdx.x * K2_ROWS;

    // cooperative h-tile load
    {
        const float4* src = (const float4*)(g_hh + row0 * HD);
        float4* dst = (float4*)&hs[0][0];
        #pragma unroll
        for (int i = 0; i < (K2_ROWS * HD / 4) / NTH2; ++i)
            dst[tid + i * NTH2] = src[tid + i * NTH2];
    }

    const bool active = (lane < 25);
    const int  oA = 2 * lane;            // 0..48
    const bool isp = (oA < NOBS);        // pair never straddles (18 even)

    ull wA[32], wB[32]; float bA = 0.0f, bB = 0.0f;
    if (active) {
        const ull* ra = (const ull*)(isp ? (Wpred + oA * HD) : (Wz + (oA - NOBS) * HD));
        const ull* rb = (const ull*)(isp ? (Wpred + (oA + 1) * HD) : (Wz + (oA + 1 - NOBS) * HD));
        #pragma unroll
        for (int k = 0; k < 32; ++k) { wA[k] = ra[k]; wB[k] = rb[k]; }
        bA = isp ? bpred[oA]     : bz[oA - NOBS];
        bB = isp ? bpred[oA + 1] : bz[oA + 1 - NOBS];
    }
    __syncthreads();

    if (!active) return;

    const size_t ZB = (size_t)BB * TT * NOBS;
    const int wr0 = warp * 16;           // 16 rows per warp

    #pragma unroll
    for (int tile = 0; tile < 4; ++tile) {
        const int r0 = wr0 + tile * 4;
        ull aA[4] = {0,0,0,0}, aB[4] = {0,0,0,0};
        #pragma unroll
        for (int k = 0; k < 16; ++k) {
            #pragma unroll
            for (int j = 0; j < 4; ++j) {
                ulonglong2 hv = ((const ulonglong2*)&hs[r0 + j][0])[k];
                FMA2(aA[j], wA[2*k],   hv.x);
                FMA2(aA[j], wA[2*k+1], hv.y);
                FMA2(aB[j], wB[2*k],   hv.x);
                FMA2(aB[j], wB[2*k+1], hv.y);
            }
        }
        #pragma unroll
        for (int j = 0; j < 4; ++j) {
            float sA = bA + lo32(aA[j]) + hi32(aA[j]);
            float sB = bB + lo32(aB[j]) + hi32(aB[j]);
            size_t row = row0 + r0 + j;
            if (isp) {
                out[row * NOBS + oA]     = fsig(sA);
                out[row * NOBS + oA + 1] = fsig(sB);
            } else {
                out[ZB + row * NZ + (oA - NOBS)]     = sA;
                out[ZB + row * NZ + (oA + 1 - NOBS)] = sB;
            }
        }
    }
}

extern "C" void kernel_launch(void* const* d_in, const int* in_sizes, int n_in,
                              void* d_out, int out_size)
{
    (void)in_sizes; (void)n_in; (void)out_size;
    const float* obs   = (const float*)d_in[0];
    const float* actp  = (const float*)d_in[1];
    const float* h0    = (const float*)d_in[2];
    const float* c0    = (const float*)d_in[3];
    const float* Wenc  = (const float*)d_in[4];
    const float* benc  = (const float*)d_in[5];
    const float* Wih   = (const float*)d_in[6];
    const float* Whh   = (const float*)d_in[7];
    const float* bih   = (const float*)d_in[8];
    const float* bhh   = (const float*)d_in[9];
    const float* Wpred = (const float*)d_in[10];
    const float* bpred = (const float*)d_in[11];
    const float* Wz    = (const float*)d_in[12];
    const float* bz    = (const float*)d_in[13];
    float* out = (float*)d_out;

    lstm_kernel<<<GRID1, NTH1>>>(obs, actp, h0, c0, Wenc, benc, Wih, Whh,
                                 bih, bhh, out);
    heads_kernel<<<GRID2, NTH2>>>(Wpred, bpred, Wz, bz, out);
}

// round 12
// speedup vs baseline: 1.7384x; 1.2164x over previous
#include <cuda_runtime.h>

typedef unsigned long long ull;

#define NOBS 18
#define NACT 5
#define HD   64
#define NZ   32
#define RB   7            // rows per block (max)
#define TT   1024
#define BB   1024
#define NTH1 512
#define GRID1 147         // ceil(1024/7); last block has 2 rows
#define HXW  (RB * 66)    // doubles per hx buffer

#define K2R    64         // rows per tile (kernel 2)
#define K2TILES 8
#define NTH2  256
#define GRID2 2048        // 2048 * 8 * 64 = 1M rows

// 256MB h-history scratch (allowed: __device__ global array)
__device__ float g_hh[(size_t)BB * TT * HD];

__device__ __forceinline__ float fsig(float x) {
    return __fdividef(1.0f, 1.0f + __expf(-x));
}
__device__ __forceinline__ float ftanh(float x) {
    float e = __expf(-2.0f * x);
    return __fdividef(1.0f - e, 1.0f + e);
}

#define FMA2(acc, a, b) \
    asm("fma.rn.f32x2 %0, %1, %2, %0;" : "+l"(acc) : "l"(a), "l"(b))

__device__ __forceinline__ float lo32(ull a) { return __uint_as_float((unsigned)a); }
__device__ __forceinline__ float hi32(ull a) { return __uint_as_float((unsigned)(a >> 32)); }
__device__ __forceinline__ ull packf(float lo, float hi) {
    return (ull)__float_as_uint(lo) | ((ull)__float_as_uint(hi) << 32);
}

// ==================== kernel 1: encoder + LSTM recurrence (fused cell) ====================
__global__ void __launch_bounds__(NTH1, 1)
lstm_kernel(const float* __restrict__ obs,  const float* __restrict__ actp,
            const float* __restrict__ h0,   const float* __restrict__ c0,
            const float* __restrict__ Wenc, const float* __restrict__ benc,
            const float* __restrict__ Wih,  const float* __restrict__ Whh,
            const float* __restrict__ bih,  const float* __restrict__ bhh,
            float* __restrict__ out)
{
    __shared__ __align__(16) double hx[2 * HXW];          // (h,x) pairs, double-buffered
    __shared__ float part[4][RB][256];                    // quarter partials
    __shared__ __align__(16) float in2[2][RB][24];        // raw inputs, double-buffered
    __shared__ __align__(8)  float Wenc_s[HD][26];
    __shared__ float benc_s[HD];

    const int tid  = threadIdx.x;
    const int row0 = blockIdx.x * RB;
    const int warp = tid >> 5, lane = tid & 31;
    const int q  = warp >> 2;                  // k-quarter 0..3
    const int ks = q * 16;
    const int gA = (warp & 3) * 64 + 2 * lane; // gates gA, gA+1

    // ---- personal gate weights: 2 gates x 16 k, packed (Whh lo, Wih hi) ----
    ull wA[16], wB[16];
    {
        const float* whA = Whh + gA * HD + ks;
        const float* wiA = Wih + gA * HD + ks;
        #pragma unroll
        for (int i = 0; i < 16; ++i) {
            wA[i] = packf(whA[i],      wiA[i]);
            wB[i] = packf(whA[HD + i], wiA[HD + i]);
        }
    }

    const int hr = tid >> 6, hu = tid & 63;    // fused-cell task (row, unit), tid<448
    float b_i = 0.f, b_f = 0.f, b_g = 0.f, b_o = 0.f;
    if (tid < 448) {
        b_i = bih[hu]       + bhh[hu];
        b_f = bih[64 + hu]  + bhh[64 + hu];
        b_g = bih[128 + hu] + bhh[128 + hu];
        b_o = bih[192 + hu] + bhh[192 + hu];
    }

    for (int i = tid; i < HD * 23; i += NTH1) Wenc_s[i / 23][i % 23] = Wenc[i];
    if (tid < HD) benc_s[tid] = benc[tid];

    if (tid < 2 * RB * 24) ((float*)in2)[tid] = 0.0f;
    for (int i = tid; i < 2 * HXW; i += NTH1) hx[i] = 0.0;   // zero both buffers
    __syncthreads();   // zero-init visible before targeted writes

    const bool rowok = (tid < 448) && (row0 + hr < BB);
    float creg = 0.f, hlast = 0.f;
    if (rowok) {
        float hv = h0[(row0 + hr) * HD + hu];
        ((float*)&hx[hr * 66 + hu])[0] = hv;    // buffer 0 = parity of t=0
        creg = c0[(row0 + hr) * HD + hu];
    }

    // ---- raw-input prefetch lanes: RB*23 = 161 ----
    float* psm0 = 0; float* psm1 = 0; const float* pg = 0; int pstr = 0;
    if (tid < RB * 23) {
        int r = tid / 23, j = tid % 23;
        if (row0 + r < BB) {
            psm0 = &in2[0][r][j]; psm1 = &in2[1][r][j];
            if (j < 18) { pg = obs  + (size_t)(row0 + r) * TT * NOBS + j;        pstr = NOBS; }
            else        { pg = actp + (size_t)(row0 + r) * TT * NACT + (j - 18); pstr = NACT; }
        }
    }

    if (psm1) *psm1 = pg[0];      // raw_0 -> in2[1] (temporary)
    __syncthreads();

    // x_0 from in2[1] -> hx[0] x-half (448 tasks)
    if (tid < 448) {
        const ull* wp = (const ull*)&Wenc_s[hu][0];
        const ull* xp = (const ull*)&in2[1][hr][0];
        ull a2 = 0ULL;
        #pragma unroll
        for (int i = 0; i < 11; ++i) FMA2(a2, wp[i], xp[i]);
        float s = fmaf(Wenc_s[hu][22], in2[1][hr][22], benc_s[hu] + lo32(a2) + hi32(a2));
        ((float*)&hx[hr * 66 + hu])[1] = fmaxf(s, 0.0f);
    }
    float pfet = 0.0f;
    if (psm0) { *psm0 = pg[pstr]; pfet = pg[2 * pstr]; }   // in2[0]=raw_1, pfet=raw_2
    __syncthreads();

    float* hist = rowok ? (g_hh + (size_t)(row0 + hr) * TT * HD + hu) : 0;

    // ================= main time loop: 2 barriers per step =================
    for (int t = 0; t < TT; ++t) {
        const double* hxp = hx + (t & 1) * HXW;        // read buffer (h_t, x_t)

        // ---- A: quarter-partial gate GEMMs (all 512 threads) ----
        {   // rows 0..3
            ull aA[4] = {0,0,0,0}, aB[4] = {0,0,0,0};
            #pragma unroll
            for (int i = 0; i < 8; ++i) {
                #pragma unroll
                for (int rr = 0; rr < 4; ++rr) {
                    ulonglong2 hv = *(const ulonglong2*)&hxp[rr * 66 + ks + 2 * i];
                    FMA2(aA[rr], wA[2*i],   hv.x);
                    FMA2(aA[rr], wA[2*i+1], hv.y);
                    FMA2(aB[rr], wB[2*i],   hv.x);
                    FMA2(aB[rr], wB[2*i+1], hv.y);
                }
            }
            #pragma unroll
            for (int rr = 0; rr < 4; ++rr) {
                float2 p;
                p.x = lo32(aA[rr]) + hi32(aA[rr]);
                p.y = lo32(aB[rr]) + hi32(aB[rr]);
                *(float2*)&part[q][rr][gA] = p;
            }
        }
        {   // rows 4..6
            ull aA[3] = {0,0,0}, aB[3] = {0,0,0};
            #pragma unroll
            for (int i = 0; i < 8; ++i) {
                #pragma unroll
                for (int rr = 0; rr < 3; ++rr) {
                    ulonglong2 hv = *(const ulonglong2*)&hxp[(4 + rr) * 66 + ks + 2 * i];
                    FMA2(aA[rr], wA[2*i],   hv.x);
                    FMA2(aA[rr], wA[2*i+1], hv.y);
                    FMA2(aB[rr], wB[2*i],   hv.x);
                    FMA2(aB[rr], wB[2*i+1], hv.y);
                }
            }
            #pragma unroll
            for (int rr = 0; rr < 3; ++rr) {
                float2 p;
                p.x = lo32(aA[rr]) + hi32(aA[rr]);
                p.y = lo32(aB[rr]) + hi32(aB[rr]);
                *(float2*)&part[q][4 + rr][gA] = p;
            }
        }
        __syncthreads();   // S0: part ready; hxp reads done

        // ---- B (fused, tid<448): encoder t+1 + reduce + nonlin + cell + store ----
        if (tid < 448) {
            // encoder for x_{t+1} from raw_{t+1} in in2[t&1]
            float xn = 0.0f;
            if (t + 1 < TT) {
                const float* xr = &in2[t & 1][hr][0];
                const ull* wp = (const ull*)&Wenc_s[hu][0];
                const ull* xp = (const ull*)xr;
                ull a2 = 0ULL;
                #pragma unroll
                for (int i = 0; i < 11; ++i) FMA2(a2, wp[i], xp[i]);
                float s = fmaf(Wenc_s[hu][22], xr[22], benc_s[hu] + lo32(a2) + hi32(a2));
                xn = fmaxf(s, 0.0f);
            }

            float pi = b_i + (part[0][hr][hu]       + part[1][hr][hu])
                           + (part[2][hr][hu]       + part[3][hr][hu]);
            float pf = b_f + (part[0][hr][64 + hu]  + part[1][hr][64 + hu])
                           + (part[2][hr][64 + hu]  + part[3][hr][64 + hu]);
            float pgt= b_g + (part[0][hr][128 + hu] + part[1][hr][128 + hu])
                           + (part[2][hr][128 + hu] + part[3][hr][128 + hu]);
            float po = b_o + (part[0][hr][192 + hu] + part[1][hr][192 + hu])
                           + (part[2][hr][192 + hu] + part[3][hr][192 + hu]);

            float si = fsig(pi), sf = fsig(pf), tg = ftanh(pgt), so = fsig(po);
            creg = sf * creg + si * tg;
            float hn = so * ftanh(creg);
            hlast = hn;

            double* slot = &hx[((t + 1) & 1) * HXW + hr * 66 + hu];
            if (t + 1 < TT) *(ull*)slot = packf(hn, xn);   // packed (h,x) store
            else            ((float*)slot)[0] = hn;
            if (hist) hist[(size_t)t * HD] = hn;

            // prefetch: raw_{t+2} -> in2[(t+1)&1]; pfet <- raw_{t+3}
            if (psm0) {
                float* pp = (t & 1) ? psm0 : psm1;
                if (t + 2 < TT) *pp = pfet;
                if (t + 3 < TT) pfet = pg[(size_t)(t + 3) * pstr];
            }
        }
        __syncthreads();   // S1: hx[(t+1)&1] + in2 ready; part reads done
    }

    // ---- epilogue: hT, cT from registers ----
    if (rowok) {
        const size_t OUT_HC = (size_t)BB * TT * (NOBS + NZ);
        out[OUT_HC + (size_t)(row0 + hr) * HD + hu] = hlast;
        out[OUT_HC + (size_t)BB * HD + (size_t)(row0 + hr) * HD + hu] = creg;
    }
}

// ==================== kernel 2: pipelined output heads (R7, unchanged) ====================
__global__ void __launch_bounds__(NTH2, 2)
heads_kernel(const float* __restrict__ Wpred, const float* __restrict__ bpred,
             const float* __restrict__ Wz,    const float* __restrict__ bz,
             float* __restrict__ out)
{
    __shared__ __align__(16) float hs[2][K2R][68];
    const int tid = threadIdx.x;
    const size_t base = (size_t)blockIdx.x * (K2R * K2TILES);

    const int o  = tid & 63;
    const int rg = tid >> 6;
    const bool active = (o < 50);
    const bool isp = (o < NOBS);

    ull w[32]; float bias = 0.0f;
    if (active) {
        const ull* wr = (const ull*)(isp ? (Wpred + o * HD) : (Wz + (o - NOBS) * HD));
        #pragma unroll
        for (int k = 0; k < 32; ++k) w[k] = wr[k];
        bias = isp ? bpred[o] : bz[o - NOBS];
    }

    {
        const float4* src = (const float4*)(g_hh + base * HD);
        #pragma unroll
        for (int i = 0; i < 4; ++i) {
            int idx = tid + i * NTH2;
            float4 v = src[idx];
            *(float4*)&hs[0][idx >> 4][(idx & 15) * 4] = v;
        }
    }
    float4 st[4];
    {
        const float4* src = (const float4*)(g_hh + (base + K2R) * HD);
        #pragma unroll
        for (int i = 0; i < 4; ++i) st[i] = src[tid + i * NTH2];
    }

    const size_t ZB = (size_t)BB * TT * NOBS;

    #pragma unroll 1
    for (int tile = 0; tile < K2TILES; ++tile) {
        __syncthreads();

        if (tile + 1 < K2TILES) {
            #pragma unroll
            for (int i = 0; i < 4; ++i) {
                int idx = tid + i * NTH2;
                *(float4*)&hs[(tile + 1) & 1][idx >> 4][(idx & 15) * 4] = st[i];
            }
        }
        if (tile + 2 < K2TILES) {
            const float4* src = (const float4*)(g_hh + (base + (size_t)(tile + 2) * K2R) * HD);
            #pragma unroll
            for (int i = 0; i < 4; ++i) st[i] = src[tid + i * NTH2];
        }

        if (active) {
            const int buf = tile & 1;
            const size_t trow0 = base + (size_t)tile * K2R + rg * 16;
            #pragma unroll
            for (int cb = 0; cb < 4; ++cb) {
                const int r0 = rg * 16 + cb * 4;
                ull a[4] = {0,0,0,0};
                #pragma unroll
                for (int k = 0; k < 16; ++k) {
                    #pragma unroll
                    for (int j = 0; j < 4; ++j) {
                        ulonglong2 hv = *(const ulonglong2*)&hs[buf][r0 + j][4 * k];
                        FMA2(a[j], w[2*k],   hv.x);
                        FMA2(a[j], w[2*k+1], hv.y);
                    }
                }
                #pragma unroll
                for (int j = 0; j < 4; ++j) {
                    float s = bias + lo32(a[j]) + hi32(a[j]);
                    size_t row = trow0 + cb * 4 + j;
                    if (isp) out[row * NOBS + o] = fsig(s);
                    else     out[ZB + row * NZ + (o - NOBS)] = s;
                }
            }
        }
    }
}

extern "C" void kernel_launch(void* const* d_in, const int* in_sizes, int n_in,
                              void* d_out, int out_size)
{
    (void)in_sizes; (void)n_in; (void)out_size;
    const float* obs   = (const float*)d_in[0];
    const float* actp  = (const float*)d_in[1];
    const float* h0    = (const float*)d_in[2];
    const float* c0    = (const float*)d_in[3];
    const float* Wenc  = (const float*)d_in[4];
    const float* benc  = (const float*)d_in[5];
    const float* Wih   = (const float*)d_in[6];
    const float* Whh   = (const float*)d_in[7];
    const float* bih   = (const float*)d_in[8];
    const float* bhh   = (const float*)d_in[9];
    const float* Wpred = (const float*)d_in[10];
    const float* bpred = (const float*)d_in[11];
    const float* Wz    = (const float*)d_in[12];
    const float* bz    = (const float*)d_in[13];
    float* out = (float*)d_out;

    lstm_kernel<<<GRID1, NTH1>>>(obs, actp, h0, c0, Wenc, benc, Wih, Whh,
                                 bih, bhh, out);
    heads_kernel<<<GRID2, NTH2>>>(Wpred, bpred, Wz, bz, out);
}